// round 9
// baseline (speedup 1.0000x reference)
#include <cuda_runtime.h>
#include <cuda_bf16.h>
#include <cstdint>
#include <math.h>

#define BATCH 8
#define NPTS  2048
#define DIM   512
#define KTOP  16
#define MCAND 32
#define SEG   (BATCH*NPTS*3)

// ---------------- static scratch ----------------
__device__ float  g_fqn[BATCH*NPTS*DIM];     // normalized ffq fp32
__device__ float  g_fpn[BATCH*NPTS*DIM];     // normalized ffp fp32
__device__ int8_t g_qi[BATCH*NPTS*DIM];      // normalized ffq int8 (per-row scale)
__device__ int8_t g_pi[BATCH*NPTS*DIM];      // normalized ffp int8 (per-row scale)
__device__ float  g_pscale[BATCH*NPTS];      // p-side row scales
__device__ int    g_cand[BATCH*NPTS*MCAND];
__device__ int    g_topi[BATCH*NPTS*KTOP];

// ---------------- ptx helpers ----------------
__device__ __forceinline__ uint32_t smem_u32(const void* p) {
    uint32_t a;
    asm("{ .reg .u64 t; cvta.to.shared.u64 t, %1; cvt.u32.u64 %0, t; }" : "=r"(a) : "l"(p));
    return a;
}
#define CP_ASYNC16(dst, src) \
    asm volatile("cp.async.cg.shared.global [%0], [%1], 16;" :: "r"(dst), "l"(src) : "memory")
#define CP_COMMIT() asm volatile("cp.async.commit_group;" ::: "memory")
#define CP_WAITN(n) asm volatile("cp.async.wait_group %0;" :: "n"(n) : "memory")

#define LDSM4(r0,r1,r2,r3, addr) \
    asm volatile("ldmatrix.sync.aligned.m8n8.x4.shared.b16 {%0,%1,%2,%3}, [%4];" \
        : "=r"(r0),"=r"(r1),"=r"(r2),"=r"(r3) : "r"(addr))

// int8 IMMA: m16n8k32, s32 accum. Byte layout of fragments matches the
// m16n8k16-bf16 ldmatrix pattern (16 rows x 32 bytes A, 32B x 8 B).
#define MMAI8(c, a0,a1,a2,a3, b0,b1) \
    asm volatile("mma.sync.aligned.m16n8k32.row.col.s32.s8.s8.s32 " \
        "{%0,%1,%2,%3},{%4,%5,%6,%7},{%8,%9},{%0,%1,%2,%3};" \
        : "+r"((c)[0]),"+r"((c)[1]),"+r"((c)[2]),"+r"((c)[3]) \
        : "r"(a0),"r"(a1),"r"(a2),"r"(a3),"r"(b0),"r"(b1))

// ---------------- kernel 0: L2-normalize -> fp32 + int8 quant ----------------
__global__ void norm_kernel(const float* __restrict__ src, int which) {
    float*  dn = which ? g_fpn : g_fqn;
    int8_t* di = which ? g_pi  : g_qi;
    int row  = blockIdx.x * 8 + (threadIdx.x >> 5);
    int lane = threadIdx.x & 31;
    if (row >= BATCH*NPTS) return;
    const float4* s = (const float4*)(src + (size_t)row * DIM);
    float4 v[4];
    float acc = 0.f;
#pragma unroll
    for (int i = 0; i < 4; ++i) {
        v[i] = s[lane + 32*i];
        acc += v[i].x*v[i].x + v[i].y*v[i].y + v[i].z*v[i].z + v[i].w*v[i].w;
    }
#pragma unroll
    for (int o = 16; o; o >>= 1) acc += __shfl_xor_sync(0xffffffffu, acc, o);
    float inv = 1.f / (sqrtf(acc) + 1e-8f);
    float amax = 0.f;
#pragma unroll
    for (int i = 0; i < 4; ++i) {
        v[i].x *= inv; v[i].y *= inv; v[i].z *= inv; v[i].w *= inv;
        amax = fmaxf(amax, fmaxf(fmaxf(fabsf(v[i].x), fabsf(v[i].y)),
                                 fmaxf(fabsf(v[i].z), fabsf(v[i].w))));
    }
#pragma unroll
    for (int o = 16; o; o >>= 1) amax = fmaxf(amax, __shfl_xor_sync(0xffffffffu, amax, o));
    float qs = 127.f / amax;
    if (which && lane == 0) g_pscale[row] = amax * (1.f/127.f);

    float4* df = (float4*)(dn + (size_t)row * DIM);
#pragma unroll
    for (int i = 0; i < 4; ++i) {
        df[lane + 32*i] = v[i];
        char4 c;
        c.x = (char)__float2int_rn(v[i].x * qs);
        c.y = (char)__float2int_rn(v[i].y * qs);
        c.z = (char)__float2int_rn(v[i].z * qs);
        c.w = (char)__float2int_rn(v[i].w * qs);
        *(char4*)&di[(size_t)row * DIM + (size_t)(lane + 32*i) * 4] = c;
    }
}

// ---------------- kernel 1: int8 IMMA GEMM + streaming top-32 ----------------
// 512 threads, 16 warps: warp tile 32x32, CTA tile 128x128, BK=128 int8 per chunk.
// 3-stage cp.async pipeline, lookahead 1, one barrier per chunk (64 chunks).
#define SM_STAGE  32768                         // A 16KB + B 16KB (128 rows x 128B)
#define SM_CS     98304                         // 3 stages
#define CS_STRIDE 132
#define SM_TOPV   (SM_CS + 128*CS_STRIDE*4)     // 165888
#define SM_TOPI   (SM_TOPV + 128*MCAND*4)       // 182272
#define SM_SSC    (SM_TOPI + 128*MCAND*4)       // 198656
#define SM_TOTAL  (SM_SSC + 128*4)              // 199168

__global__ __launch_bounds__(512, 1) void gemm_topm() {
    extern __shared__ char sm[];
    float* Cs    = (float*)(sm + SM_CS);
    float* stopv = (float*)(sm + SM_TOPV);
    int*   stopi = (int*)(sm + SM_TOPI);
    float* ssc   = (float*)(sm + SM_SSC);
    const uint32_t smb = smem_u32(sm);
    const int tid  = threadIdx.x, lane = tid & 31, warp = tid >> 5;
    const int batch = blockIdx.y, q0 = blockIdx.x * 128;

    if (tid < 128) {
#pragma unroll
        for (int j = 0; j < MCAND; ++j) { stopv[tid*MCAND + j] = -INFINITY; stopi[tid*MCAND + j] = 0; }
    }
    float thmin = -INFINITY; int minpos = 0;

    // producer: threads 0-255 -> A, 256-511 -> B; thread pair per 128B row-chunk
    const int  pr  = (tid & 255) >> 1;
    const bool isB = tid >= 256;
    const int  cc  = (tid & 1) * 4;
    const int8_t* abase  = g_qi + (size_t)(batch*NPTS + q0 + pr) * DIM;
    const int8_t* bbase0 = g_pi + (size_t)(batch*NPTS + pr) * DIM;
    uint32_t pswz[4];
#pragma unroll
    for (int c = 0; c < 4; ++c) {
        uint32_t off = (uint32_t)pr*128 + (cc + c)*16;
        pswz[c] = (off ^ ((off >> 3) & 0x70)) + (isB ? 16384u : 0u);
    }

    // consumer fragment offsets (within a stage); warp tile 32x32
    const int wm = warp >> 2, wn = warp & 3;
    uint32_t aOff[2], bOff[2];
    {
        int ar = wm*32 + (lane & 15);
        uint32_t acb = (uint32_t)(lane >> 4) * 16;
#pragma unroll
        for (int mf = 0; mf < 2; ++mf) {
            uint32_t off = (uint32_t)(ar + mf*16)*128 + acb;
            aOff[mf] = off ^ ((off >> 3) & 0x70);
        }
        int br = wn*32 + (lane & 7) + ((lane & 16) >> 1);
        uint32_t bcb = (uint32_t)(lane & 8) * 2;
#pragma unroll
        for (int h = 0; h < 2; ++h) {
            uint32_t off = (uint32_t)(br + h*16)*128 + bcb;
            bOff[h] = 16384u + (off ^ ((off >> 3) & 0x70));
        }
    }

    int acc[2][4][4];
#pragma unroll
    for (int i = 0; i < 2; ++i)
#pragma unroll
        for (int j = 0; j < 4; ++j)
#pragma unroll
            for (int r = 0; r < 4; ++r) acc[i][j][r] = 0;

    // prologue: issue chunk 0 into stage 0
    {
        const char* src = (const char*)(isB ? bbase0 : abase) + cc*16;
#pragma unroll
        for (int c = 0; c < 4; ++c) CP_ASYNC16(smb + pswz[c], src + c*16);
        CP_COMMIT();
    }

    for (int g = 0; g < 64; ++g) {            // g = nt*4 + kc ; chunk = 128 K-int8
        if (g + 1 < 64) {
            int gn = g + 1;
            int nt = gn >> 2, kc = gn & 3;
            const char* src = (const char*)(isB ? (bbase0 + (size_t)nt*128*DIM) : abase)
                              + kc*128 + cc*16;
            uint32_t dst = smb + (uint32_t)(gn % 3) * SM_STAGE;
#pragma unroll
            for (int c = 0; c < 4; ++c) CP_ASYNC16(dst + pswz[c], src + c*16);
            CP_COMMIT();
            CP_WAITN(1);
        } else {
            CP_WAITN(0);
        }
        __syncthreads();

        // compute chunk g: 4 x k32 steps
        {
            const uint32_t sbase = smb + (uint32_t)(g % 3) * SM_STAGE;
#pragma unroll
            for (int k32 = 0; k32 < 4; ++k32) {
                const uint32_t kx = (uint32_t)k32 << 5;
                uint32_t a[8], b[8];
#pragma unroll
                for (int mf = 0; mf < 2; ++mf)
                    LDSM4(a[mf*4+0], a[mf*4+1], a[mf*4+2], a[mf*4+3], sbase + (aOff[mf] ^ kx));
#pragma unroll
                for (int h = 0; h < 2; ++h)
                    LDSM4(b[h*4+0], b[h*4+1], b[h*4+2], b[h*4+3], sbase + (bOff[h] ^ kx));
#pragma unroll
                for (int mf = 0; mf < 2; ++mf)
#pragma unroll
                    for (int nf = 0; nf < 4; ++nf) {
                        int bb = (nf >> 1)*4 + (nf & 1)*2;
                        MMAI8(acc[mf][nf], a[mf*4+0], a[mf*4+1], a[mf*4+2], a[mf*4+3],
                              b[bb], b[bb+1]);
                    }
            }
        }

        if ((g & 3) == 3) {
            // epilogue for n-tile nt (uniform branch)
            const int nt = g >> 2;
            const int gid = lane >> 2, tig = lane & 3;
#pragma unroll
            for (int mf = 0; mf < 2; ++mf)
#pragma unroll
                for (int nf = 0; nf < 4; ++nf) {
                    int r0 = wm*32 + mf*16 + gid;
                    int c0 = wn*32 + nf*8 + tig*2;
                    Cs[r0*CS_STRIDE + c0]       = (float)acc[mf][nf][0];
                    Cs[r0*CS_STRIDE + c0 + 1]   = (float)acc[mf][nf][1];
                    Cs[(r0+8)*CS_STRIDE + c0]   = (float)acc[mf][nf][2];
                    Cs[(r0+8)*CS_STRIDE + c0+1] = (float)acc[mf][nf][3];
                    acc[mf][nf][0] = acc[mf][nf][1] = acc[mf][nf][2] = acc[mf][nf][3] = 0;
                }
            if (tid < 128) ssc[tid] = g_pscale[batch*NPTS + nt*128 + tid];
            __syncthreads();
            if (tid < 128) {
                const float4* row = (const float4*)&Cs[tid*CS_STRIDE];
                const float4* scv = (const float4*)ssc;
                const int pbase = nt * 128;
                for (int j = 0; j < 32; ++j) {
                    float4 v4 = row[j];
                    float4 s4 = scv[j];
                    float vv[4] = {v4.x*s4.x, v4.y*s4.y, v4.z*s4.z, v4.w*s4.w};
                    float m4 = fmaxf(fmaxf(vv[0], vv[1]), fmaxf(vv[2], vv[3]));
                    if (m4 > thmin) {
#pragma unroll
                        for (int e = 0; e < 4; ++e) {
                            float v = vv[e];
                            if (v > thmin) {
                                stopv[tid*MCAND + minpos] = v;
                                stopi[tid*MCAND + minpos] = pbase + j*4 + e;
                                float mn = stopv[tid*MCAND]; int mp = 0;
#pragma unroll 8
                                for (int u = 1; u < MCAND; ++u) {
                                    float x = stopv[tid*MCAND + u];
                                    if (x < mn) { mn = x; mp = u; }
                                }
                                thmin = mn; minpos = mp;
                            }
                        }
                    }
                }
            }
        }
    }

    if (tid < 128) {
        size_t base = (size_t)(batch*NPTS + q0 + tid) * MCAND;
#pragma unroll
        for (int j = 0; j < MCAND; ++j) g_cand[base + j] = stopi[tid*MCAND + j];
    }
}

// ---------------- kernel 2: exact rescore, R1-bit-identical sequential fma ----
#define RS_CHUNK 128
__global__ __launch_bounds__(256) void rescore_kernel(float* __restrict__ out) {
    __shared__ int   sidx[MCAND];
    __shared__ float sfq[2][RS_CHUNK];
    __shared__ float sp[2][RS_CHUNK*33];
    const int qi    = blockIdx.x;          // 0..16383
    const int batch = qi >> 11;
    const int tid   = threadIdx.x, lane = tid & 31, warp = tid >> 5;

    if (tid < MCAND) sidx[tid] = g_cand[(size_t)qi*MCAND + tid];
    __syncthreads();

    const float* fq  = g_fqn + (size_t)qi * DIM;
    const float* fpb = g_fpn + (size_t)batch*NPTS*DIM;

    auto load_tile = [&](int buf, int ch, int tileid) {
        int row = (tileid & 7)*4 + (lane >> 3);
        int k4  = (tileid >> 3)*8 + (lane & 7);
        float4 v = *(const float4*)(fpb + (size_t)sidx[row]*DIM + ch*RS_CHUNK + k4*4);
        float* b = &sp[buf][0];
        b[(k4*4+0)*33 + row] = v.x;
        b[(k4*4+1)*33 + row] = v.y;
        b[(k4*4+2)*33 + row] = v.z;
        b[(k4*4+3)*33 + row] = v.w;
    };

    {
#pragma unroll
        for (int it = 0; it < 4; ++it) load_tile(0, 0, warp*4 + it);
        if (tid < 32) {
            float4 v = *(const float4*)(fq + tid*4);
            *(float4*)&sfq[0][tid*4] = v;
        }
    }
    __syncthreads();

    float acc = 0.f;
#pragma unroll
    for (int ch = 0; ch < DIM/RS_CHUNK; ++ch) {
        const int buf = ch & 1;
        if (warp == 0) {
            const float* b = &sp[buf][0];
            const float* f = &sfq[buf][0];
#pragma unroll
            for (int k = 0; k < RS_CHUNK; ++k)
                acc = fmaf(f[k], b[k*33 + lane], acc);   // strict k order
        } else if (ch + 1 < DIM/RS_CHUNK) {
            const int nb = buf ^ 1, wl = warp - 1;
#pragma unroll
            for (int it = 0; it < 5; ++it) {
                int tileid = wl*5 + it;
                if (tileid < 32) load_tile(nb, ch + 1, tileid);
            }
            if (warp == 7) {
                float4 v = *(const float4*)(fq + (ch+1)*RS_CHUNK + lane*4);
                *(float4*)&sfq[nb][lane*4] = v;
            }
        }
        __syncthreads();
    }

    if (warp == 0) {
        float v = acc; int idx = sidx[lane];
#pragma unroll
        for (int k = 2; k <= 32; k <<= 1) {
#pragma unroll
            for (int j = k >> 1; j > 0; j >>= 1) {
                float pv = __shfl_xor_sync(0xffffffffu, v, j);
                int   pi = __shfl_xor_sync(0xffffffffu, idx, j);
                bool up    = (lane & k) == 0;
                bool lower = (lane & j) == 0;
                bool pb    = (pv > v) || (pv == v && pi < idx);
                bool take  = (pb == (up == lower));
                if (take) { v = pv; idx = pi; }
            }
        }
        if (lane < KTOP) {
            g_topi[(size_t)qi*KTOP + lane] = idx;
            out[3*SEG + (size_t)qi*KTOP + lane] = (float)idx;
        }
    }
}

// ---------------- kernel 3: gather + pool + linear + rotate-back ------------
__device__ __forceinline__ void inv3(const float* __restrict__ R, float* o) {
    float a = R[0], b = R[1], c = R[2];
    float d = R[3], e = R[4], f = R[5];
    float g = R[6], h = R[7], i = R[8];
    float A =  (e*i - f*h);
    float Bc = -(d*i - f*g);
    float Cc =  (d*h - e*g);
    float det = a*A + b*Bc + c*Cc;
    float id = 1.f / det;
    o[0] = A*id;             o[1] = -(b*i - c*h)*id;  o[2] =  (b*f - c*e)*id;
    o[3] = Bc*id;            o[4] =  (a*i - c*g)*id;  o[5] = -(a*f - c*d)*id;
    o[6] = Cc*id;            o[7] = -(a*h - b*g)*id;  o[8] =  (a*e - b*d)*id;
}

__global__ void post_kernel(const float* __restrict__ q,
                            const float* __restrict__ ffq,
                            const float* __restrict__ ffp,
                            const float* __restrict__ R1,
                            const float* __restrict__ R2,
                            const int*   __restrict__ centroids,
                            const float* __restrict__ W,
                            const float* __restrict__ bias,
                            float* __restrict__ out) {
    const int pt    = blockIdx.x;
    const int batch = pt >> 11;
    const int tid   = threadIdx.x;       // 128 threads

    __shared__ int   sidx[KTOP];
    __shared__ float sred[3][4];

    if (tid < KTOP) sidx[tid] = g_topi[(size_t)pt*KTOP + tid];
    __syncthreads();

    const float* fpb = ffp + (size_t)batch*NPTS*DIM;
    float pv0 = 0.f, pv1 = 0.f, pv2 = 0.f;
#pragma unroll
    for (int r = 0; r < 4; ++r) {
        int d = tid + r*128;
        float fq = ffq[(size_t)pt*DIM + d];
        float s = 0.f, mx = -INFINITY;
#pragma unroll
        for (int k = 0; k < KTOP; ++k) {
            float v = fpb[(size_t)sidx[k]*DIM + d];
            s += v;
            mx = fmaxf(mx, v);
        }
        float avg = s * (1.f/KTOP);
        pv0 += W[0*1536 + d]*fq + W[0*1536 + 512 + d]*avg + W[0*1536 + 1024 + d]*mx;
        pv1 += W[1*1536 + d]*fq + W[1*1536 + 512 + d]*avg + W[1*1536 + 1024 + d]*mx;
        pv2 += W[2*1536 + d]*fq + W[2*1536 + 512 + d]*avg + W[2*1536 + 1024 + d]*mx;
    }
#pragma unroll
    for (int o = 16; o; o >>= 1) {
        pv0 += __shfl_xor_sync(0xffffffffu, pv0, o);
        pv1 += __shfl_xor_sync(0xffffffffu, pv1, o);
        pv2 += __shfl_xor_sync(0xffffffffu, pv2, o);
    }
    int lane = tid & 31, w = tid >> 5;
    if (lane == 0) { sred[0][w] = pv0; sred[1][w] = pv1; sred[2][w] = pv2; }
    __syncthreads();

    if (tid == 0) {
        float v0 = sred[0][0]+sred[0][1]+sred[0][2]+sred[0][3] + bias[0];
        float v1 = sred[1][0]+sred[1][1]+sred[1][2]+sred[1][3] + bias[1];
        float v2 = sred[2][0]+sred[2][1]+sred[2][2]+sred[2][3] + bias[2];
        float i1[9], i2[9];
        inv3(R1 + (size_t)pt*9, i1);
        inv3(R2 + (size_t)pt*9, i2);
        float t0 = i1[0]*v0 + i1[1]*v1 + i1[2]*v2;
        float t1 = i1[3]*v0 + i1[4]*v1 + i1[5]*v2;
        float t2 = i1[6]*v0 + i1[7]*v1 + i1[8]*v2;
        float r0 = i2[0]*t0 + i2[1]*t1 + i2[2]*t2;
        float r1 = i2[3]*t0 + i2[4]*t1 + i2[5]*t2;
        float r2 = i2[6]*t0 + i2[7]*t1 + i2[8]*t2;
        float m = (centroids[pt] >= NPTS) ? 1.f : 0.f;
        const float* qp = q + (size_t)pt*3;
        float o0 = qp[0] + r0*m;
        float o1 = qp[1] + r1*m;
        float o2 = qp[2] + r2*m;
        out[1*SEG + pt*3 + 0] = o0;
        out[1*SEG + pt*3 + 1] = o1;
        out[1*SEG + pt*3 + 2] = o2;
        out[2*SEG + pt*3 + 0] = o0;
        out[2*SEG + pt*3 + 1] = o1;
        out[2*SEG + pt*3 + 2] = o2;
    }
}

// ---------------- launch -----------------------------------------------------
extern "C" void kernel_launch(void* const* d_in, const int* in_sizes, int n_in,
                              void* d_out, int out_size) {
    const float* q    = (const float*)d_in[1];
    const float* ffp  = (const float*)d_in[2];
    const float* ffq  = (const float*)d_in[3];
    const float* R1   = (const float*)d_in[4];
    const float* R2   = (const float*)d_in[5];
    const int*   cent = (const int*)  d_in[6];
    const float* W    = (const float*)d_in[7];
    const float* bias = (const float*)d_in[8];
    float* out = (float*)d_out;

    cudaMemcpyAsync(out, q, (size_t)SEG*sizeof(float), cudaMemcpyDeviceToDevice);

    norm_kernel<<<BATCH*NPTS/8, 256>>>(ffq, 0);
    norm_kernel<<<BATCH*NPTS/8, 256>>>(ffp, 1);

    cudaFuncSetAttribute(gemm_topm,
                         cudaFuncAttributeMaxDynamicSharedMemorySize, SM_TOTAL);
    gemm_topm<<<dim3(NPTS/128, BATCH), 512, SM_TOTAL>>>();

    rescore_kernel<<<BATCH*NPTS, 256>>>(out);

    post_kernel<<<BATCH*NPTS, 128>>>(q, ffq, ffp, R1, R2, cent, W, bias, out);
}

// round 10
// speedup vs baseline: 1.0879x; 1.0879x over previous
#include <cuda_runtime.h>
#include <cuda_bf16.h>
#include <cstdint>
#include <math.h>

#define BATCH 8
#define NPTS  2048
#define DIM   512
#define KTOP  16
#define MCAND 32
#define SEG   (BATCH*NPTS*3)

// ---------------- static scratch ----------------
__device__ float g_fqn[BATCH*NPTS*DIM];          // normalized ffq fp32
__device__ float g_fpn[BATCH*NPTS*DIM];          // normalized ffp fp32
__device__ __nv_bfloat16 g_qb[BATCH*NPTS*DIM];   // normalized ffq bf16
__device__ __nv_bfloat16 g_pb[BATCH*NPTS*DIM];   // normalized ffp bf16
__device__ int g_cand[BATCH*NPTS*MCAND];
__device__ int g_topi[BATCH*NPTS*KTOP];

// ---------------- ptx helpers ----------------
__device__ __forceinline__ uint32_t smem_u32(const void* p) {
    uint32_t a;
    asm("{ .reg .u64 t; cvta.to.shared.u64 t, %1; cvt.u32.u64 %0, t; }" : "=r"(a) : "l"(p));
    return a;
}
#define CP_ASYNC16(dst, src) \
    asm volatile("cp.async.cg.shared.global [%0], [%1], 16;" :: "r"(dst), "l"(src) : "memory")
#define CP_COMMIT() asm volatile("cp.async.commit_group;" ::: "memory")
#define CP_WAITN(n) asm volatile("cp.async.wait_group %0;" :: "n"(n) : "memory")

#define LDSM4(r0,r1,r2,r3, addr) \
    asm volatile("ldmatrix.sync.aligned.m8n8.x4.shared.b16 {%0,%1,%2,%3}, [%4];" \
        : "=r"(r0),"=r"(r1),"=r"(r2),"=r"(r3) : "r"(addr))

#define MMA16816(c, a0,a1,a2,a3, b0,b1) \
    asm volatile("mma.sync.aligned.m16n8k16.row.col.f32.bf16.bf16.f32 " \
        "{%0,%1,%2,%3},{%4,%5,%6,%7},{%8,%9},{%0,%1,%2,%3};" \
        : "+f"((c)[0]),"+f"((c)[1]),"+f"((c)[2]),"+f"((c)[3]) \
        : "r"(a0),"r"(a1),"r"(a2),"r"(a3),"r"(b0),"r"(b1))

// ---------------- kernel 0: L2-normalize -> fp32 + bf16 ----------------
__global__ void norm_kernel(const float* __restrict__ src, int which) {
    float* dn = which ? g_fpn : g_fqn;
    __nv_bfloat16* db = which ? g_pb : g_qb;
    int row  = blockIdx.x * 8 + (threadIdx.x >> 5);
    int lane = threadIdx.x & 31;
    if (row >= BATCH*NPTS) return;
    const float4* s = (const float4*)(src + (size_t)row * DIM);
    float4 v[4];
    float acc = 0.f;
#pragma unroll
    for (int i = 0; i < 4; ++i) {
        v[i] = s[lane + 32*i];
        acc += v[i].x*v[i].x + v[i].y*v[i].y + v[i].z*v[i].z + v[i].w*v[i].w;
    }
#pragma unroll
    for (int o = 16; o; o >>= 1) acc += __shfl_xor_sync(0xffffffffu, acc, o);
    float inv = 1.f / (sqrtf(acc) + 1e-8f);
    float4* df = (float4*)(dn + (size_t)row * DIM);
#pragma unroll
    for (int i = 0; i < 4; ++i) {
        float4 w = v[i];
        w.x *= inv; w.y *= inv; w.z *= inv; w.w *= inv;
        df[lane + 32*i] = w;
        size_t off = (size_t)row * DIM + (size_t)(lane + 32*i) * 4;
        *(__nv_bfloat162*)&db[off]   = __floats2bfloat162_rn(w.x, w.y);
        *(__nv_bfloat162*)&db[off+2] = __floats2bfloat162_rn(w.z, w.w);
    }
}

// ---------------- kernel 1: bf16 HMMA GEMM + streaming top-32 ----------------
// CTA tile M64 x N128, BK=64 (128B rows). 256 threads, 8 warps (warp tile 32x32,
// 2x4 grid). 2-stage cp.async pipeline, 2 barriers per chunk (WAR-safe).
// 2 CTAs per SM so barrier/epilogue stalls in one CTA overlap the other's MMAs.
#define SM_ASZ    8192                           // A: 64 rows x 128B
#define SM_STAGE  24576                          // A 8KB + B 16KB
#define SM_CS     49152                          // after 2 stages
#define CS_STRIDE 132
#define SM_TOPV   (SM_CS + 64*CS_STRIDE*4)       // 82944
#define SM_TOPI   (SM_TOPV + 64*MCAND*4)         // 91136
#define SM_TOTAL  (SM_TOPI + 64*MCAND*4)         // 99328

__global__ __launch_bounds__(256, 2) void gemm_topm() {
    extern __shared__ char sm[];
    float* Cs    = (float*)(sm + SM_CS);
    float* stopv = (float*)(sm + SM_TOPV);
    int*   stopi = (int*)(sm + SM_TOPI);
    const uint32_t smb = smem_u32(sm);
    const int tid  = threadIdx.x, lane = tid & 31, warp = tid >> 5;
    const int batch = blockIdx.y, q0 = blockIdx.x * 64;

    if (tid < 64) {
#pragma unroll
        for (int j = 0; j < MCAND; ++j) { stopv[tid*MCAND + j] = -INFINITY; stopi[tid*MCAND + j] = 0; }
    }
    float thmin = -INFINITY; int minpos = 0;

    // producers: A (tid<128): thread-pair per query row; B (all 256): pair per point row
    const int  prA = tid >> 1;            // 0..63  (valid when tid<128)
    const int  prB = tid >> 1;            // 0..127
    const int  cc  = (tid & 1) * 4;
    const __nv_bfloat16* abase  = g_qb + (size_t)(batch*NPTS + q0 + (prA & 63)) * DIM;
    const __nv_bfloat16* bbase0 = g_pb + (size_t)(batch*NPTS + prB) * DIM;
    uint32_t aswz[4], bswz[4];
#pragma unroll
    for (int c = 0; c < 4; ++c) {
        uint32_t offA = (uint32_t)(prA & 63)*128 + (cc + c)*16;
        aswz[c] = offA ^ ((offA >> 3) & 0x70);
        uint32_t offB = (uint32_t)prB*128 + (cc + c)*16;
        bswz[c] = (uint32_t)SM_ASZ + (offB ^ ((offB >> 3) & 0x70));
    }

    // consumer fragment offsets (within a stage); warp tile 32x32; wm in 0..1, wn in 0..3
    const int wm = warp >> 2, wn = warp & 3;
    uint32_t aOff[2], bOff[2];
    {
        int ar = wm*32 + (lane & 15);
        uint32_t acb = (uint32_t)(lane >> 4) * 16;
#pragma unroll
        for (int mf = 0; mf < 2; ++mf) {
            uint32_t off = (uint32_t)(ar + mf*16)*128 + acb;
            aOff[mf] = off ^ ((off >> 3) & 0x70);
        }
        int br = wn*32 + (lane & 7) + ((lane & 16) >> 1);
        uint32_t bcb = (uint32_t)(lane & 8) * 2;
#pragma unroll
        for (int h = 0; h < 2; ++h) {
            uint32_t off = (uint32_t)(br + h*16)*128 + bcb;
            bOff[h] = (uint32_t)SM_ASZ + (off ^ ((off >> 3) & 0x70));
        }
    }

    float acc[2][4][4];
#pragma unroll
    for (int i = 0; i < 2; ++i)
#pragma unroll
        for (int j = 0; j < 4; ++j)
#pragma unroll
            for (int r = 0; r < 4; ++r) acc[i][j][r] = 0.f;

    // prologue: issue chunk 0 into stage 0
    {
        if (tid < 128) {
            const char* srcA = (const char*)abase + cc*16;
#pragma unroll
            for (int c = 0; c < 4; ++c) CP_ASYNC16(smb + aswz[c], srcA + c*16);
        }
        const char* srcB = (const char*)bbase0 + cc*16;
#pragma unroll
        for (int c = 0; c < 4; ++c) CP_ASYNC16(smb + bswz[c], srcB + c*16);
        CP_COMMIT();
    }

    for (int g = 0; g < 128; ++g) {           // g = nt*8 + kc ; 16 n-tiles x 8 k-chunks
        if (g + 1 < 128) {
            int gn = g + 1;
            int nt = gn >> 3, kc = gn & 7;
            uint32_t dst = smb + (uint32_t)(gn & 1) * SM_STAGE;
            if (tid < 128) {
                const char* srcA = (const char*)abase + kc*128 + cc*16;
#pragma unroll
                for (int c = 0; c < 4; ++c) CP_ASYNC16(dst + aswz[c], srcA + c*16);
            }
            const char* srcB = (const char*)(bbase0 + (size_t)nt*128*DIM) + kc*128 + cc*16;
#pragma unroll
            for (int c = 0; c < 4; ++c) CP_ASYNC16(dst + bswz[c], srcB + c*16);
            CP_COMMIT();
            CP_WAITN(1);
        } else {
            CP_WAITN(0);
        }
        __syncthreads();   // chunk g data visible to all

        // compute chunk g
        {
            const uint32_t sbase = smb + (uint32_t)(g & 1) * SM_STAGE;
#pragma unroll
            for (int k16 = 0; k16 < 4; ++k16) {
                const uint32_t kx = (uint32_t)k16 << 5;
                uint32_t a[8], b[8];
#pragma unroll
                for (int mf = 0; mf < 2; ++mf)
                    LDSM4(a[mf*4+0], a[mf*4+1], a[mf*4+2], a[mf*4+3], sbase + (aOff[mf] ^ kx));
#pragma unroll
                for (int h = 0; h < 2; ++h)
                    LDSM4(b[h*4+0], b[h*4+1], b[h*4+2], b[h*4+3], sbase + (bOff[h] ^ kx));
#pragma unroll
                for (int mf = 0; mf < 2; ++mf)
#pragma unroll
                    for (int nf = 0; nf < 4; ++nf) {
                        int bb = (nf >> 1)*4 + (nf & 1)*2;
                        MMA16816(acc[mf][nf], a[mf*4+0], a[mf*4+1], a[mf*4+2], a[mf*4+3],
                                 b[bb], b[bb+1]);
                    }
            }
        }

        if ((g & 7) == 7) {
            // epilogue for n-tile nt (uniform branch)
            const int nt = g >> 3;
            const int gid = lane >> 2, tig = lane & 3;
#pragma unroll
            for (int mf = 0; mf < 2; ++mf)
#pragma unroll
                for (int nf = 0; nf < 4; ++nf) {
                    int r0 = wm*32 + mf*16 + gid;
                    int c0 = wn*32 + nf*8 + tig*2;
                    Cs[r0*CS_STRIDE + c0]       = acc[mf][nf][0];
                    Cs[r0*CS_STRIDE + c0 + 1]   = acc[mf][nf][1];
                    Cs[(r0+8)*CS_STRIDE + c0]   = acc[mf][nf][2];
                    Cs[(r0+8)*CS_STRIDE + c0+1] = acc[mf][nf][3];
                    acc[mf][nf][0] = acc[mf][nf][1] = acc[mf][nf][2] = acc[mf][nf][3] = 0.f;
                }
            __syncthreads();
            if (tid < 64) {
                const float4* row = (const float4*)&Cs[tid*CS_STRIDE];
                const int pbase = nt * 128;
                for (int j = 0; j < 32; ++j) {
                    float4 v4 = row[j];
                    float m4 = fmaxf(fmaxf(v4.x, v4.y), fmaxf(v4.z, v4.w));
                    if (m4 > thmin) {
                        float vv[4] = {v4.x, v4.y, v4.z, v4.w};
#pragma unroll
                        for (int e = 0; e < 4; ++e) {
                            float v = vv[e];
                            if (v > thmin) {
                                stopv[tid*MCAND + minpos] = v;
                                stopi[tid*MCAND + minpos] = pbase + j*4 + e;
                                float mn = stopv[tid*MCAND]; int mp = 0;
#pragma unroll 8
                                for (int u = 1; u < MCAND; ++u) {
                                    float x = stopv[tid*MCAND + u];
                                    if (x < mn) { mn = x; mp = u; }
                                }
                                thmin = mn; minpos = mp;
                            }
                        }
                    }
                }
            }
        }
        __syncthreads();   // WAR: all reads of stage (g&1) done before next issue
    }

    if (tid < 64) {
        size_t base = (size_t)(batch*NPTS + q0 + tid) * MCAND;
#pragma unroll
        for (int j = 0; j < MCAND; ++j) g_cand[base + j] = stopi[tid*MCAND + j];
    }
}

// ---------------- kernel 2: exact rescore, R1-bit-identical sequential fma ----
#define RS_CHUNK 128
__global__ __launch_bounds__(256) void rescore_kernel(float* __restrict__ out) {
    __shared__ int   sidx[MCAND];
    __shared__ float sfq[2][RS_CHUNK];
    __shared__ float sp[2][RS_CHUNK*33];
    const int qi    = blockIdx.x;          // 0..16383
    const int batch = qi >> 11;
    const int tid   = threadIdx.x, lane = tid & 31, warp = tid >> 5;

    if (tid < MCAND) sidx[tid] = g_cand[(size_t)qi*MCAND + tid];
    __syncthreads();

    const float* fq  = g_fqn + (size_t)qi * DIM;
    const float* fpb = g_fpn + (size_t)batch*NPTS*DIM;

    auto load_tile = [&](int buf, int ch, int tileid) {
        int row = (tileid & 7)*4 + (lane >> 3);
        int k4  = (tileid >> 3)*8 + (lane & 7);
        float4 v = *(const float4*)(fpb + (size_t)sidx[row]*DIM + ch*RS_CHUNK + k4*4);
        float* b = &sp[buf][0];
        b[(k4*4+0)*33 + row] = v.x;
        b[(k4*4+1)*33 + row] = v.y;
        b[(k4*4+2)*33 + row] = v.z;
        b[(k4*4+3)*33 + row] = v.w;
    };

    {
#pragma unroll
        for (int it = 0; it < 4; ++it) load_tile(0, 0, warp*4 + it);
        if (tid < 32) {
            float4 v = *(const float4*)(fq + tid*4);
            *(float4*)&sfq[0][tid*4] = v;
        }
    }
    __syncthreads();

    float acc = 0.f;
#pragma unroll
    for (int ch = 0; ch < DIM/RS_CHUNK; ++ch) {
        const int buf = ch & 1;
        if (warp == 0) {
            const float* b = &sp[buf][0];
            const float* f = &sfq[buf][0];
#pragma unroll
            for (int k = 0; k < RS_CHUNK; ++k)
                acc = fmaf(f[k], b[k*33 + lane], acc);   // strict k order
        } else if (ch + 1 < DIM/RS_CHUNK) {
            const int nb = buf ^ 1, wl = warp - 1;
#pragma unroll
            for (int it = 0; it < 5; ++it) {
                int tileid = wl*5 + it;
                if (tileid < 32) load_tile(nb, ch + 1, tileid);
            }
            if (warp == 7) {
                float4 v = *(const float4*)(fq + (ch+1)*RS_CHUNK + lane*4);
                *(float4*)&sfq[nb][lane*4] = v;
            }
        }
        __syncthreads();
    }

    if (warp == 0) {
        float v = acc; int idx = sidx[lane];
#pragma unroll
        for (int k = 2; k <= 32; k <<= 1) {
#pragma unroll
            for (int j = k >> 1; j > 0; j >>= 1) {
                float pv = __shfl_xor_sync(0xffffffffu, v, j);
                int   pi = __shfl_xor_sync(0xffffffffu, idx, j);
                bool up    = (lane & k) == 0;
                bool lower = (lane & j) == 0;
                bool pb    = (pv > v) || (pv == v && pi < idx);
                bool take  = (pb == (up == lower));
                if (take) { v = pv; idx = pi; }
            }
        }
        if (lane < KTOP) {
            g_topi[(size_t)qi*KTOP + lane] = idx;
            out[3*SEG + (size_t)qi*KTOP + lane] = (float)idx;
        }
    }
}

// ---------------- kernel 3: gather + pool + linear + rotate-back ------------
__device__ __forceinline__ void inv3(const float* __restrict__ R, float* o) {
    float a = R[0], b = R[1], c = R[2];
    float d = R[3], e = R[4], f = R[5];
    float g = R[6], h = R[7], i = R[8];
    float A =  (e*i - f*h);
    float Bc = -(d*i - f*g);
    float Cc =  (d*h - e*g);
    float det = a*A + b*Bc + c*Cc;
    float id = 1.f / det;
    o[0] = A*id;             o[1] = -(b*i - c*h)*id;  o[2] =  (b*f - c*e)*id;
    o[3] = Bc*id;            o[4] =  (a*i - c*g)*id;  o[5] = -(a*f - c*d)*id;
    o[6] = Cc*id;            o[7] = -(a*h - b*g)*id;  o[8] =  (a*e - b*d)*id;
}

__global__ void post_kernel(const float* __restrict__ q,
                            const float* __restrict__ ffq,
                            const float* __restrict__ ffp,
                            const float* __restrict__ R1,
                            const float* __restrict__ R2,
                            const int*   __restrict__ centroids,
                            const float* __restrict__ W,
                            const float* __restrict__ bias,
                            float* __restrict__ out) {
    const int pt    = blockIdx.x;
    const int batch = pt >> 11;
    const int tid   = threadIdx.x;       // 128 threads

    __shared__ int   sidx[KTOP];
    __shared__ float sred[3][4];

    if (tid < KTOP) sidx[tid] = g_topi[(size_t)pt*KTOP + tid];
    __syncthreads();

    const float* fpb = ffp + (size_t)batch*NPTS*DIM;
    float pv0 = 0.f, pv1 = 0.f, pv2 = 0.f;
#pragma unroll
    for (int r = 0; r < 4; ++r) {
        int d = tid + r*128;
        float fq = ffq[(size_t)pt*DIM + d];
        float s = 0.f, mx = -INFINITY;
#pragma unroll
        for (int k = 0; k < KTOP; ++k) {
            float v = fpb[(size_t)sidx[k]*DIM + d];
            s += v;
            mx = fmaxf(mx, v);
        }
        float avg = s * (1.f/KTOP);
        pv0 += W[0*1536 + d]*fq + W[0*1536 + 512 + d]*avg + W[0*1536 + 1024 + d]*mx;
        pv1 += W[1*1536 + d]*fq + W[1*1536 + 512 + d]*avg + W[1*1536 + 1024 + d]*mx;
        pv2 += W[2*1536 + d]*fq + W[2*1536 + 512 + d]*avg + W[2*1536 + 1024 + d]*mx;
    }
#pragma unroll
    for (int o = 16; o; o >>= 1) {
        pv0 += __shfl_xor_sync(0xffffffffu, pv0, o);
        pv1 += __shfl_xor_sync(0xffffffffu, pv1, o);
        pv2 += __shfl_xor_sync(0xffffffffu, pv2, o);
    }
    int lane = tid & 31, w = tid >> 5;
    if (lane == 0) { sred[0][w] = pv0; sred[1][w] = pv1; sred[2][w] = pv2; }
    __syncthreads();

    if (tid == 0) {
        float v0 = sred[0][0]+sred[0][1]+sred[0][2]+sred[0][3] + bias[0];
        float v1 = sred[1][0]+sred[1][1]+sred[1][2]+sred[1][3] + bias[1];
        float v2 = sred[2][0]+sred[2][1]+sred[2][2]+sred[2][3] + bias[2];
        float i1[9], i2[9];
        inv3(R1 + (size_t)pt*9, i1);
        inv3(R2 + (size_t)pt*9, i2);
        float t0 = i1[0]*v0 + i1[1]*v1 + i1[2]*v2;
        float t1 = i1[3]*v0 + i1[4]*v1 + i1[5]*v2;
        float t2 = i1[6]*v0 + i1[7]*v1 + i1[8]*v2;
        float r0 = i2[0]*t0 + i2[1]*t1 + i2[2]*t2;
        float r1 = i2[3]*t0 + i2[4]*t1 + i2[5]*t2;
        float r2 = i2[6]*t0 + i2[7]*t1 + i2[8]*t2;
        float m = (centroids[pt] >= NPTS) ? 1.f : 0.f;
        const float* qp = q + (size_t)pt*3;
        float o0 = qp[0] + r0*m;
        float o1 = qp[1] + r1*m;
        float o2 = qp[2] + r2*m;
        out[1*SEG + pt*3 + 0] = o0;
        out[1*SEG + pt*3 + 1] = o1;
        out[1*SEG + pt*3 + 2] = o2;
        out[2*SEG + pt*3 + 0] = o0;
        out[2*SEG + pt*3 + 1] = o1;
        out[2*SEG + pt*3 + 2] = o2;
    }
}

// ---------------- launch -----------------------------------------------------
extern "C" void kernel_launch(void* const* d_in, const int* in_sizes, int n_in,
                              void* d_out, int out_size) {
    const float* q    = (const float*)d_in[1];
    const float* ffp  = (const float*)d_in[2];
    const float* ffq  = (const float*)d_in[3];
    const float* R1   = (const float*)d_in[4];
    const float* R2   = (const float*)d_in[5];
    const int*   cent = (const int*)  d_in[6];
    const float* W    = (const float*)d_in[7];
    const float* bias = (const float*)d_in[8];
    float* out = (float*)d_out;

    cudaMemcpyAsync(out, q, (size_t)SEG*sizeof(float), cudaMemcpyDeviceToDevice);

    norm_kernel<<<BATCH*NPTS/8, 256>>>(ffq, 0);
    norm_kernel<<<BATCH*NPTS/8, 256>>>(ffp, 1);

    cudaFuncSetAttribute(gemm_topm,
                         cudaFuncAttributeMaxDynamicSharedMemorySize, SM_TOTAL);
    gemm_topm<<<dim3(NPTS/64, BATCH), 256, SM_TOTAL>>>();

    rescore_kernel<<<BATCH*NPTS, 256>>>(out);

    post_kernel<<<BATCH*NPTS, 128>>>(q, ffq, ffp, R1, R2, cent, W, bias, out);
}

// round 11
// speedup vs baseline: 1.1387x; 1.0467x over previous
#include <cuda_runtime.h>
#include <cuda_fp16.h>
#include <cstdint>
#include <math.h>

#define BATCH 8
#define NPTS  2048
#define DIM   512
#define KTOP  16
#define MCAND 32
#define SEG   (BATCH*NPTS*3)

// ---------------- static scratch ----------------
__device__ float  g_fqn[BATCH*NPTS*DIM];     // normalized ffq fp32
__device__ float  g_fpn[BATCH*NPTS*DIM];     // normalized ffp fp32
__device__ __half g_qh[BATCH*NPTS*DIM];      // normalized ffq fp16
__device__ __half g_ph[BATCH*NPTS*DIM];      // normalized ffp fp16
__device__ int    g_cand[BATCH*NPTS*MCAND];
__device__ int    g_topi[BATCH*NPTS*KTOP];

// ---------------- ptx helpers ----------------
__device__ __forceinline__ uint32_t smem_u32(const void* p) {
    uint32_t a;
    asm("{ .reg .u64 t; cvta.to.shared.u64 t, %1; cvt.u32.u64 %0, t; }" : "=r"(a) : "l"(p));
    return a;
}
#define CP_ASYNC16(dst, src) \
    asm volatile("cp.async.cg.shared.global [%0], [%1], 16;" :: "r"(dst), "l"(src) : "memory")
#define CP_COMMIT() asm volatile("cp.async.commit_group;" ::: "memory")
#define CP_WAITN(n) asm volatile("cp.async.wait_group %0;" :: "n"(n) : "memory")

#define LDSM4(r0,r1,r2,r3, addr) \
    asm volatile("ldmatrix.sync.aligned.m8n8.x4.shared.b16 {%0,%1,%2,%3}, [%4];" \
        : "=r"(r0),"=r"(r1),"=r"(r2),"=r"(r3) : "r"(addr))

// fp16 MMA with fp16 accumulator (2x legacy-pipe rate): D,C = 2 x f16x2 regs
#define MMAF16(c, a0,a1,a2,a3, b0,b1) \
    asm volatile("mma.sync.aligned.m16n8k16.row.col.f16.f16.f16.f16 " \
        "{%0,%1},{%2,%3,%4,%5},{%6,%7},{%0,%1};" \
        : "+r"((c)[0]),"+r"((c)[1]) \
        : "r"(a0),"r"(a1),"r"(a2),"r"(a3),"r"(b0),"r"(b1))

// ---------------- kernel 0: L2-normalize -> fp32 + fp16 ----------------
__global__ void norm_kernel(const float* __restrict__ src, int which) {
    float*  dn = which ? g_fpn : g_fqn;
    __half* dh = which ? g_ph  : g_qh;
    int row  = blockIdx.x * 8 + (threadIdx.x >> 5);
    int lane = threadIdx.x & 31;
    if (row >= BATCH*NPTS) return;
    const float4* s = (const float4*)(src + (size_t)row * DIM);
    float4 v[4];
    float acc = 0.f;
#pragma unroll
    for (int i = 0; i < 4; ++i) {
        v[i] = s[lane + 32*i];
        acc += v[i].x*v[i].x + v[i].y*v[i].y + v[i].z*v[i].z + v[i].w*v[i].w;
    }
#pragma unroll
    for (int o = 16; o; o >>= 1) acc += __shfl_xor_sync(0xffffffffu, acc, o);
    float inv = 1.f / (sqrtf(acc) + 1e-8f);
    float4* df = (float4*)(dn + (size_t)row * DIM);
#pragma unroll
    for (int i = 0; i < 4; ++i) {
        float4 w = v[i];
        w.x *= inv; w.y *= inv; w.z *= inv; w.w *= inv;
        df[lane + 32*i] = w;
        size_t off = (size_t)row * DIM + (size_t)(lane + 32*i) * 4;
        *(__half2*)&dh[off]   = __floats2half2_rn(w.x, w.y);
        *(__half2*)&dh[off+2] = __floats2half2_rn(w.z, w.w);
    }
}

// ---------------- kernel 1: fp16 HMMA GEMM + streaming top-32 ----------------
// 512 threads, 16 warps: warp tile 32x32 (4x4 warp grid), CTA tile 128x128, BK=64.
// 3-stage cp.async pipeline, lookahead 1, one barrier per K-chunk.
#define SM_STAGE  32768                         // A 16KB + B 16KB
#define SM_CS     98304                         // 3 stages
#define CS_STRIDE 132
#define SM_TOPV   (SM_CS + 128*CS_STRIDE*4)     // 165888
#define SM_TOPI   (SM_TOPV + 128*MCAND*4)       // 182272
#define SM_TOTAL  (SM_TOPI + 128*MCAND*4)       // 198656

__global__ __launch_bounds__(512, 1) void gemm_topm() {
    extern __shared__ char sm[];
    float* Cs    = (float*)(sm + SM_CS);
    float* stopv = (float*)(sm + SM_TOPV);
    int*   stopi = (int*)(sm + SM_TOPI);
    const uint32_t smb = smem_u32(sm);
    const int tid  = threadIdx.x, lane = tid & 31, warp = tid >> 5;
    const int batch = blockIdx.y, q0 = blockIdx.x * 128;

    if (tid < 128) {
#pragma unroll
        for (int j = 0; j < MCAND; ++j) { stopv[tid*MCAND + j] = -INFINITY; stopi[tid*MCAND + j] = 0; }
    }
    float thmin = -INFINITY; int minpos = 0;

    // producer: threads 0-255 -> A, 256-511 -> B; thread pair per 128B row
    const int  pr  = (tid & 255) >> 1;
    const bool isB = tid >= 256;
    const int  cc  = (tid & 1) * 4;
    const __half* abase  = g_qh + (size_t)(batch*NPTS + q0 + pr) * DIM;
    const __half* bbase0 = g_ph + (size_t)(batch*NPTS + pr) * DIM;
    uint32_t pswz[4];
#pragma unroll
    for (int c = 0; c < 4; ++c) {
        uint32_t off = (uint32_t)pr*128 + (cc + c)*16;
        pswz[c] = (off ^ ((off >> 3) & 0x70)) + (isB ? 16384u : 0u);
    }

    // consumer fragment offsets (within a stage); warp tile 32x32
    const int wm = warp >> 2, wn = warp & 3;
    uint32_t aOff[2], bOff[2];
    {
        int ar = wm*32 + (lane & 15);
        uint32_t acb = (uint32_t)(lane >> 4) * 16;
#pragma unroll
        for (int mf = 0; mf < 2; ++mf) {
            uint32_t off = (uint32_t)(ar + mf*16)*128 + acb;
            aOff[mf] = off ^ ((off >> 3) & 0x70);
        }
        int br = wn*32 + (lane & 7) + ((lane & 16) >> 1);
        uint32_t bcb = (uint32_t)(lane & 8) * 2;
#pragma unroll
        for (int h = 0; h < 2; ++h) {
            uint32_t off = (uint32_t)(br + h*16)*128 + bcb;
            bOff[h] = 16384u + (off ^ ((off >> 3) & 0x70));
        }
    }

    uint32_t acc[2][4][2];   // packed f16x2 accumulators
#pragma unroll
    for (int i = 0; i < 2; ++i)
#pragma unroll
        for (int j = 0; j < 4; ++j) { acc[i][j][0] = 0u; acc[i][j][1] = 0u; }

    // prologue: issue chunk 0 into stage 0
    {
        const char* src = (const char*)(isB ? bbase0 : abase) + cc*16;
#pragma unroll
        for (int c = 0; c < 4; ++c) CP_ASYNC16(smb + pswz[c], src + c*16);
        CP_COMMIT();
    }

    for (int g = 0; g < 128; ++g) {           // g = nt*8 + kc
        if (g + 1 < 128) {
            int gn = g + 1;
            int nt = gn >> 3, kc = gn & 7;
            const char* src = (const char*)(isB ? (bbase0 + (size_t)nt*128*DIM) : abase)
                              + kc*128 + cc*16;
            uint32_t dst = smb + (uint32_t)(gn % 3) * SM_STAGE;
#pragma unroll
            for (int c = 0; c < 4; ++c) CP_ASYNC16(dst + pswz[c], src + c*16);
            CP_COMMIT();
            CP_WAITN(1);
        } else {
            CP_WAITN(0);
        }
        __syncthreads();

        // compute chunk g
        {
            const uint32_t sbase = smb + (uint32_t)(g % 3) * SM_STAGE;
#pragma unroll
            for (int k16 = 0; k16 < 4; ++k16) {
                const uint32_t kx = (uint32_t)k16 << 5;
                uint32_t a[8], b[8];
#pragma unroll
                for (int mf = 0; mf < 2; ++mf)
                    LDSM4(a[mf*4+0], a[mf*4+1], a[mf*4+2], a[mf*4+3], sbase + (aOff[mf] ^ kx));
#pragma unroll
                for (int h = 0; h < 2; ++h)
                    LDSM4(b[h*4+0], b[h*4+1], b[h*4+2], b[h*4+3], sbase + (bOff[h] ^ kx));
#pragma unroll
                for (int mf = 0; mf < 2; ++mf)
#pragma unroll
                    for (int nf = 0; nf < 4; ++nf) {
                        int bb = (nf >> 1)*4 + (nf & 1)*2;
                        MMAF16(acc[mf][nf], a[mf*4+0], a[mf*4+1], a[mf*4+2], a[mf*4+3],
                               b[bb], b[bb+1]);
                    }
            }
        }

        if ((g & 7) == 7) {
            // epilogue for n-tile nt (uniform branch)
            const int nt = g >> 3;
            const int gid = lane >> 2, tig = lane & 3;
#pragma unroll
            for (int mf = 0; mf < 2; ++mf)
#pragma unroll
                for (int nf = 0; nf < 4; ++nf) {
                    int r0 = wm*32 + mf*16 + gid;
                    int c0 = wn*32 + nf*8 + tig*2;
                    float2 f01 = __half22float2(*(__half2*)&acc[mf][nf][0]);
                    float2 f23 = __half22float2(*(__half2*)&acc[mf][nf][1]);
                    Cs[r0*CS_STRIDE + c0]       = f01.x;
                    Cs[r0*CS_STRIDE + c0 + 1]   = f01.y;
                    Cs[(r0+8)*CS_STRIDE + c0]   = f23.x;
                    Cs[(r0+8)*CS_STRIDE + c0+1] = f23.y;
                    acc[mf][nf][0] = 0u; acc[mf][nf][1] = 0u;
                }
            __syncthreads();
            if (tid < 128) {
                const float4* row = (const float4*)&Cs[tid*CS_STRIDE];
                const int pbase = nt * 128;
                for (int j = 0; j < 32; ++j) {
                    float4 v4 = row[j];
                    float m4 = fmaxf(fmaxf(v4.x, v4.y), fmaxf(v4.z, v4.w));
                    if (m4 > thmin) {
                        float vv[4] = {v4.x, v4.y, v4.z, v4.w};
#pragma unroll
                        for (int e = 0; e < 4; ++e) {
                            float v = vv[e];
                            if (v > thmin) {
                                stopv[tid*MCAND + minpos] = v;
                                stopi[tid*MCAND + minpos] = pbase + j*4 + e;
                                float mn = stopv[tid*MCAND]; int mp = 0;
#pragma unroll 8
                                for (int u = 1; u < MCAND; ++u) {
                                    float x = stopv[tid*MCAND + u];
                                    if (x < mn) { mn = x; mp = u; }
                                }
                                thmin = mn; minpos = mp;
                            }
                        }
                    }
                }
            }
        }
    }

    if (tid < 128) {
        size_t base = (size_t)(batch*NPTS + q0 + tid) * MCAND;
#pragma unroll
        for (int j = 0; j < MCAND; ++j) g_cand[base + j] = stopi[tid*MCAND + j];
    }
}

// ---------------- kernel 2: exact rescore, R1-bit-identical sequential fma ----
#define RS_CHUNK 128
__global__ __launch_bounds__(256) void rescore_kernel(float* __restrict__ out) {
    __shared__ int   sidx[MCAND];
    __shared__ float sfq[2][RS_CHUNK];
    __shared__ float sp[2][RS_CHUNK*33];
    const int qi    = blockIdx.x;          // 0..16383
    const int batch = qi >> 11;
    const int tid   = threadIdx.x, lane = tid & 31, warp = tid >> 5;

    if (tid < MCAND) sidx[tid] = g_cand[(size_t)qi*MCAND + tid];
    __syncthreads();

    const float* fq  = g_fqn + (size_t)qi * DIM;
    const float* fpb = g_fpn + (size_t)batch*NPTS*DIM;

    auto load_tile = [&](int buf, int ch, int tileid) {
        int row = (tileid & 7)*4 + (lane >> 3);
        int k4  = (tileid >> 3)*8 + (lane & 7);
        float4 v = *(const float4*)(fpb + (size_t)sidx[row]*DIM + ch*RS_CHUNK + k4*4);
        float* b = &sp[buf][0];
        b[(k4*4+0)*33 + row] = v.x;
        b[(k4*4+1)*33 + row] = v.y;
        b[(k4*4+2)*33 + row] = v.z;
        b[(k4*4+3)*33 + row] = v.w;
    };

    {
#pragma unroll
        for (int it = 0; it < 4; ++it) load_tile(0, 0, warp*4 + it);
        if (tid < 32) {
            float4 v = *(const float4*)(fq + tid*4);
            *(float4*)&sfq[0][tid*4] = v;
        }
    }
    __syncthreads();

    float acc = 0.f;
#pragma unroll
    for (int ch = 0; ch < DIM/RS_CHUNK; ++ch) {
        const int buf = ch & 1;
        if (warp == 0) {
            const float* b = &sp[buf][0];
            const float* f = &sfq[buf][0];
#pragma unroll
            for (int k = 0; k < RS_CHUNK; ++k)
                acc = fmaf(f[k], b[k*33 + lane], acc);   // strict k order
        } else if (ch + 1 < DIM/RS_CHUNK) {
            const int nb = buf ^ 1, wl = warp - 1;
#pragma unroll
            for (int it = 0; it < 5; ++it) {
                int tileid = wl*5 + it;
                if (tileid < 32) load_tile(nb, ch + 1, tileid);
            }
            if (warp == 7) {
                float4 v = *(const float4*)(fq + (ch+1)*RS_CHUNK + lane*4);
                *(float4*)&sfq[nb][lane*4] = v;
            }
        }
        __syncthreads();
    }

    if (warp == 0) {
        float v = acc; int idx = sidx[lane];
#pragma unroll
        for (int k = 2; k <= 32; k <<= 1) {
#pragma unroll
            for (int j = k >> 1; j > 0; j >>= 1) {
                float pv = __shfl_xor_sync(0xffffffffu, v, j);
                int   pi = __shfl_xor_sync(0xffffffffu, idx, j);
                bool up    = (lane & k) == 0;
                bool lower = (lane & j) == 0;
                bool pb    = (pv > v) || (pv == v && pi < idx);
                bool take  = (pb == (up == lower));
                if (take) { v = pv; idx = pi; }
            }
        }
        if (lane < KTOP) {
            g_topi[(size_t)qi*KTOP + lane] = idx;
            out[3*SEG + (size_t)qi*KTOP + lane] = (float)idx;
        }
    }
}

// ---------------- kernel 3: gather + pool + linear + rotate-back ------------
__device__ __forceinline__ void inv3(const float* __restrict__ R, float* o) {
    float a = R[0], b = R[1], c = R[2];
    float d = R[3], e = R[4], f = R[5];
    float g = R[6], h = R[7], i = R[8];
    float A =  (e*i - f*h);
    float Bc = -(d*i - f*g);
    float Cc =  (d*h - e*g);
    float det = a*A + b*Bc + c*Cc;
    float id = 1.f / det;
    o[0] = A*id;             o[1] = -(b*i - c*h)*id;  o[2] =  (b*f - c*e)*id;
    o[3] = Bc*id;            o[4] =  (a*i - c*g)*id;  o[5] = -(a*f - c*d)*id;
    o[6] = Cc*id;            o[7] = -(a*h - b*g)*id;  o[8] =  (a*e - b*d)*id;
}

__global__ void post_kernel(const float* __restrict__ q,
                            const float* __restrict__ ffq,
                            const float* __restrict__ ffp,
                            const float* __restrict__ R1,
                            const float* __restrict__ R2,
                            const int*   __restrict__ centroids,
                            const float* __restrict__ W,
                            const float* __restrict__ bias,
                            float* __restrict__ out) {
    const int pt    = blockIdx.x;
    const int batch = pt >> 11;
    const int tid   = threadIdx.x;       // 128 threads

    __shared__ int   sidx[KTOP];
    __shared__ float sred[3][4];

    if (tid < KTOP) sidx[tid] = g_topi[(size_t)pt*KTOP + tid];
    __syncthreads();

    const float* fpb = ffp + (size_t)batch*NPTS*DIM;
    float pv0 = 0.f, pv1 = 0.f, pv2 = 0.f;
#pragma unroll
    for (int r = 0; r < 4; ++r) {
        int d = tid + r*128;
        float fq = ffq[(size_t)pt*DIM + d];
        float s = 0.f, mx = -INFINITY;
#pragma unroll
        for (int k = 0; k < KTOP; ++k) {
            float v = fpb[(size_t)sidx[k]*DIM + d];
            s += v;
            mx = fmaxf(mx, v);
        }
        float avg = s * (1.f/KTOP);
        pv0 += W[0*1536 + d]*fq + W[0*1536 + 512 + d]*avg + W[0*1536 + 1024 + d]*mx;
        pv1 += W[1*1536 + d]*fq + W[1*1536 + 512 + d]*avg + W[1*1536 + 1024 + d]*mx;
        pv2 += W[2*1536 + d]*fq + W[2*1536 + 512 + d]*avg + W[2*1536 + 1024 + d]*mx;
    }
#pragma unroll
    for (int o = 16; o; o >>= 1) {
        pv0 += __shfl_xor_sync(0xffffffffu, pv0, o);
        pv1 += __shfl_xor_sync(0xffffffffu, pv1, o);
        pv2 += __shfl_xor_sync(0xffffffffu, pv2, o);
    }
    int lane = tid & 31, w = tid >> 5;
    if (lane == 0) { sred[0][w] = pv0; sred[1][w] = pv1; sred[2][w] = pv2; }
    __syncthreads();

    if (tid == 0) {
        float v0 = sred[0][0]+sred[0][1]+sred[0][2]+sred[0][3] + bias[0];
        float v1 = sred[1][0]+sred[1][1]+sred[1][2]+sred[1][3] + bias[1];
        float v2 = sred[2][0]+sred[2][1]+sred[2][2]+sred[2][3] + bias[2];
        float i1[9], i2[9];
        inv3(R1 + (size_t)pt*9, i1);
        inv3(R2 + (size_t)pt*9, i2);
        float t0 = i1[0]*v0 + i1[1]*v1 + i1[2]*v2;
        float t1 = i1[3]*v0 + i1[4]*v1 + i1[5]*v2;
        float t2 = i1[6]*v0 + i1[7]*v1 + i1[8]*v2;
        float r0 = i2[0]*t0 + i2[1]*t1 + i2[2]*t2;
        float r1 = i2[3]*t0 + i2[4]*t1 + i2[5]*t2;
        float r2 = i2[6]*t0 + i2[7]*t1 + i2[8]*t2;
        float m = (centroids[pt] >= NPTS) ? 1.f : 0.f;
        const float* qp = q + (size_t)pt*3;
        float o0 = qp[0] + r0*m;
        float o1 = qp[1] + r1*m;
        float o2 = qp[2] + r2*m;
        out[1*SEG + pt*3 + 0] = o0;
        out[1*SEG + pt*3 + 1] = o1;
        out[1*SEG + pt*3 + 2] = o2;
        out[2*SEG + pt*3 + 0] = o0;
        out[2*SEG + pt*3 + 1] = o1;
        out[2*SEG + pt*3 + 2] = o2;
    }
}

// ---------------- launch -----------------------------------------------------
extern "C" void kernel_launch(void* const* d_in, const int* in_sizes, int n_in,
                              void* d_out, int out_size) {
    const float* q    = (const float*)d_in[1];
    const float* ffp  = (const float*)d_in[2];
    const float* ffq  = (const float*)d_in[3];
    const float* R1   = (const float*)d_in[4];
    const float* R2   = (const float*)d_in[5];
    const int*   cent = (const int*)  d_in[6];
    const float* W    = (const float*)d_in[7];
    const float* bias = (const float*)d_in[8];
    float* out = (float*)d_out;

    cudaMemcpyAsync(out, q, (size_t)SEG*sizeof(float), cudaMemcpyDeviceToDevice);

    norm_kernel<<<BATCH*NPTS/8, 256>>>(ffq, 0);
    norm_kernel<<<BATCH*NPTS/8, 256>>>(ffp, 1);

    cudaFuncSetAttribute(gemm_topm,
                         cudaFuncAttributeMaxDynamicSharedMemorySize, SM_TOTAL);
    gemm_topm<<<dim3(NPTS/128, BATCH), 512, SM_TOTAL>>>();

    rescore_kernel<<<BATCH*NPTS, 256>>>(out);

    post_kernel<<<BATCH*NPTS, 128>>>(q, ffq, ffp, R1, R2, cent, W, bias, out);
}

// round 12
// speedup vs baseline: 1.2000x; 1.0538x over previous
#include <cuda_runtime.h>
#include <cuda_bf16.h>
#include <cstdint>
#include <math.h>

#define BATCH 8
#define NPTS  2048
#define DIM   512
#define KTOP  16
#define MCAND 32
#define SEG   (BATCH*NPTS*3)

// ---------------- static scratch ----------------
__device__ __align__(256) float g_fqn[BATCH*NPTS*DIM];   // normalized ffq fp32 (linear)
__device__ __align__(256) float g_fpn[BATCH*NPTS*DIM];   // normalized ffp fp32 (linear)
// bf16 operands in TILED + PRE-SWIZZLED layout:
// tile(b, rb, kc) = 16KB: 128 rows x 64 bf16 (128B/row), SW128 swizzle baked in.
// tile offset = ((b*16 + rb)*8 + kc) * 16384 bytes.
__device__ __align__(256) __nv_bfloat16 g_qt[BATCH*NPTS*DIM];
__device__ __align__(256) __nv_bfloat16 g_pt[BATCH*NPTS*DIM];
__device__ int g_cand[BATCH*NPTS*MCAND];
__device__ int g_topi[BATCH*NPTS*KTOP];

// ---------------- ptx helpers ----------------
__device__ __forceinline__ uint32_t smem_u32(const void* p) {
    uint32_t a;
    asm("{ .reg .u64 t; cvta.to.shared.u64 t, %1; cvt.u32.u64 %0, t; }" : "=r"(a) : "l"(p));
    return a;
}
#define MBAR_INIT(mb, cnt) \
    asm volatile("mbarrier.init.shared.b64 [%0], %1;" :: "r"(mb), "r"(cnt) : "memory")
#define MBAR_EXPECT_TX(mb, bytes) \
    asm volatile("mbarrier.arrive.expect_tx.shared.b64 _, [%0], %1;" :: "r"(mb), "r"(bytes) : "memory")
#define MBAR_WAIT(mb, par) do {                                                        \
    uint32_t _d;                                                                       \
    asm volatile("{ .reg .pred p; mbarrier.try_wait.parity.acquire.cta.shared::cta.b64 p, [%1], %2;" \
                 " selp.b32 %0,1,0,p; }" : "=r"(_d) : "r"(mb), "r"(par) : "memory");   \
    if (!_d) {                                                                         \
        asm volatile("{ .reg .pred P1;\n"                                              \
            "WL_%=: mbarrier.try_wait.parity.acquire.cta.shared::cta.b64 P1, [%0], %1, 0x989680;\n" \
            "@P1 bra WD_%=;\n bra WL_%=;\nWD_%=: }" :: "r"(mb), "r"(par) : "memory");  \
    } } while (0)
#define CP_BULK(dst, src, sz, mb) \
    asm volatile("cp.async.bulk.shared::cta.global.mbarrier::complete_tx::bytes [%0], [%1], %2, [%3];" \
        :: "r"(dst), "l"(src), "r"(sz), "r"(mb) : "memory")

#define LDSM4(r0,r1,r2,r3, addr) \
    asm volatile("ldmatrix.sync.aligned.m8n8.x4.shared.b16 {%0,%1,%2,%3}, [%4];" \
        : "=r"(r0),"=r"(r1),"=r"(r2),"=r"(r3) : "r"(addr))

#define MMA16816(c, a0,a1,a2,a3, b0,b1) \
    asm volatile("mma.sync.aligned.m16n8k16.row.col.f32.bf16.bf16.f32 " \
        "{%0,%1,%2,%3},{%4,%5,%6,%7},{%8,%9},{%0,%1,%2,%3};" \
        : "+f"((c)[0]),"+f"((c)[1]),"+f"((c)[2]),"+f"((c)[3]) \
        : "r"(a0),"r"(a1),"r"(a2),"r"(a3),"r"(b0),"r"(b1))

// ---------------- kernel 0: L2-normalize -> fp32 linear + bf16 tiled-swizzled --
__global__ void norm_kernel(const float* __restrict__ src, int which) {
    float* dn = which ? g_fpn : g_fqn;
    char*  dt = (char*)(which ? g_pt : g_qt);
    int row  = blockIdx.x * 8 + (threadIdx.x >> 5);
    int lane = threadIdx.x & 31;
    if (row >= BATCH*NPTS) return;
    const float4* s = (const float4*)(src + (size_t)row * DIM);
    float4 v[4];
    float acc = 0.f;
#pragma unroll
    for (int i = 0; i < 4; ++i) {
        v[i] = s[lane + 32*i];
        acc += v[i].x*v[i].x + v[i].y*v[i].y + v[i].z*v[i].z + v[i].w*v[i].w;
    }
#pragma unroll
    for (int o = 16; o; o >>= 1) acc += __shfl_xor_sync(0xffffffffu, acc, o);
    float inv = 1.f / (sqrtf(acc) + 1e-8f);

    const int b  = row >> 11;
    const int n  = row & 2047;
    const int rb = n >> 7;
    const int r  = n & 127;
    float4* df = (float4*)(dn + (size_t)row * DIM);
#pragma unroll
    for (int i = 0; i < 4; ++i) {
        float4 w = v[i];
        w.x *= inv; w.y *= inv; w.z *= inv; w.w *= inv;
        df[lane + 32*i] = w;
        // tiled + swizzled bf16 write (8 bytes, stays inside one 16B swizzle unit)
        int e0   = (lane + 32*i) * 4;        // first element index in row
        int kc   = e0 >> 6;
        int ec   = e0 & 63;
        uint32_t byte = (uint32_t)r*128 + (uint32_t)ec*2;
        uint32_t sw   = byte ^ ((byte >> 3) & 0x70);
        char* dst = dt + ((size_t)((b*16 + rb)*8 + kc))*16384 + sw;
        *(__nv_bfloat162*)(dst)     = __floats2bfloat162_rn(w.x, w.y);
        *(__nv_bfloat162*)(dst + 4) = __floats2bfloat162_rn(w.z, w.w);
    }
}

// ---------------- kernel 1: bf16 HMMA GEMM + streaming top-32 ----------------
// 512 threads, 16 warps: warp tile 32x32, CTA tile 128x128, BK=64.
// Stage fill = 2 x cp.async.bulk (16KB A-tile + 16KB B-tile) via TMA engine,
// mbarrier complete_tx. 3 stages, lookahead 1, one barrier per chunk.
#define SM_STAGE  32768                         // A 16KB + B 16KB
#define SM_CS     98304                         // 3 stages
#define CS_STRIDE 132
#define SM_TOPV   (SM_CS + 128*CS_STRIDE*4)     // 165888
#define SM_TOPI   (SM_TOPV + 128*MCAND*4)       // 182272
#define SM_MBAR   (SM_TOPI + 128*MCAND*4)       // 198656
#define SM_TOTAL  (SM_MBAR + 64)                // 198720

__global__ __launch_bounds__(512, 1) void gemm_topm() {
    extern __shared__ char sm[];
    float* Cs    = (float*)(sm + SM_CS);
    float* stopv = (float*)(sm + SM_TOPV);
    int*   stopi = (int*)(sm + SM_TOPI);
    const uint32_t smb = smem_u32(sm);
    const uint32_t mb0 = smb + SM_MBAR;
    const int tid  = threadIdx.x, lane = tid & 31, warp = tid >> 5;
    const int batch = blockIdx.y, qb = blockIdx.x;   // qb = row-block of queries

    if (tid == 0) {
        MBAR_INIT(mb0 +  0, 1);
        MBAR_INIT(mb0 +  8, 1);
        MBAR_INIT(mb0 + 16, 1);
    }
    if (tid < 128) {
#pragma unroll
        for (int j = 0; j < MCAND; ++j) { stopv[tid*MCAND + j] = -INFINITY; stopi[tid*MCAND + j] = 0; }
    }
    float thmin = -INFINITY; int minpos = 0;

    const char* atiles = (const char*)g_qt + ((size_t)(batch*16 + qb))*8*16384;
    const char* ptbase = (const char*)g_pt + ((size_t)batch*16)*8*16384;

    // consumer fragment offsets (within a stage); warp tile 32x32
    const int wm = warp >> 2, wn = warp & 3;
    uint32_t aOff[2], bOff[2];
    {
        int ar = wm*32 + (lane & 15);
        uint32_t acb = (uint32_t)(lane >> 4) * 16;
#pragma unroll
        for (int mf = 0; mf < 2; ++mf) {
            uint32_t off = (uint32_t)(ar + mf*16)*128 + acb;
            aOff[mf] = off ^ ((off >> 3) & 0x70);
        }
        int br = wn*32 + (lane & 7) + ((lane & 16) >> 1);
        uint32_t bcb = (uint32_t)(lane & 8) * 2;
#pragma unroll
        for (int h = 0; h < 2; ++h) {
            uint32_t off = (uint32_t)(br + h*16)*128 + bcb;
            bOff[h] = 16384u + (off ^ ((off >> 3) & 0x70));
        }
    }

    float acc[2][4][4];
#pragma unroll
    for (int i = 0; i < 2; ++i)
#pragma unroll
        for (int j = 0; j < 4; ++j)
#pragma unroll
            for (int r = 0; r < 4; ++r) acc[i][j][r] = 0.f;

    __syncthreads();   // mbarrier init visible

    // prologue: issue chunk 0 into stage 0
    if (tid == 0) {
        MBAR_EXPECT_TX(mb0, 32768u);
        CP_BULK(smb,          atiles,  16384u, mb0);             // A tile kc=0
        CP_BULK(smb + 16384u, ptbase,  16384u, mb0);             // B tile nt=0, kc=0
    }

    for (int g = 0; g < 128; ++g) {           // g = nt*8 + kc
        if (g + 1 < 128) {
            if (tid == 0) {
                int gn = g + 1;
                int nt = gn >> 3, kc = gn & 7;
                uint32_t mb  = mb0 + (uint32_t)(gn % 3) * 8;
                uint32_t dst = smb + (uint32_t)(gn % 3) * SM_STAGE;
                MBAR_EXPECT_TX(mb, 32768u);
                CP_BULK(dst,          atiles + (size_t)kc*16384, 16384u, mb);
                CP_BULK(dst + 16384u, ptbase + ((size_t)nt*8 + kc)*16384, 16384u, mb);
            }
        }
        // wait for chunk g data
        MBAR_WAIT(mb0 + (uint32_t)(g % 3) * 8, (uint32_t)((g / 3) & 1));

        // compute chunk g
        {
            const uint32_t sbase = smb + (uint32_t)(g % 3) * SM_STAGE;
#pragma unroll
            for (int k16 = 0; k16 < 4; ++k16) {
                const uint32_t kx = (uint32_t)k16 << 5;
                uint32_t a[8], b[8];
#pragma unroll
                for (int mf = 0; mf < 2; ++mf)
                    LDSM4(a[mf*4+0], a[mf*4+1], a[mf*4+2], a[mf*4+3], sbase + (aOff[mf] ^ kx));
#pragma unroll
                for (int h = 0; h < 2; ++h)
                    LDSM4(b[h*4+0], b[h*4+1], b[h*4+2], b[h*4+3], sbase + (bOff[h] ^ kx));
#pragma unroll
                for (int mf = 0; mf < 2; ++mf)
#pragma unroll
                    for (int nf = 0; nf < 4; ++nf) {
                        int bb = (nf >> 1)*4 + (nf & 1)*2;
                        MMA16816(acc[mf][nf], a[mf*4+0], a[mf*4+1], a[mf*4+2], a[mf*4+3],
                                 b[bb], b[bb+1]);
                    }
            }
        }

        if ((g & 7) == 7) {
            // epilogue for n-tile nt (uniform branch)
            const int nt = g >> 3;
            const int gid = lane >> 2, tig = lane & 3;
#pragma unroll
            for (int mf = 0; mf < 2; ++mf)
#pragma unroll
                for (int nf = 0; nf < 4; ++nf) {
                    int r0 = wm*32 + mf*16 + gid;
                    int c0 = wn*32 + nf*8 + tig*2;
                    Cs[r0*CS_STRIDE + c0]       = acc[mf][nf][0];
                    Cs[r0*CS_STRIDE + c0 + 1]   = acc[mf][nf][1];
                    Cs[(r0+8)*CS_STRIDE + c0]   = acc[mf][nf][2];
                    Cs[(r0+8)*CS_STRIDE + c0+1] = acc[mf][nf][3];
                    acc[mf][nf][0] = acc[mf][nf][1] = acc[mf][nf][2] = acc[mf][nf][3] = 0.f;
                }
            __syncthreads();
            if (tid < 128) {
                const float4* row = (const float4*)&Cs[tid*CS_STRIDE];
                const int pbase = nt * 128;
                for (int j = 0; j < 32; ++j) {
                    float4 v4 = row[j];
                    float m4 = fmaxf(fmaxf(v4.x, v4.y), fmaxf(v4.z, v4.w));
                    if (m4 > thmin) {
                        float vv[4] = {v4.x, v4.y, v4.z, v4.w};
#pragma unroll
                        for (int e = 0; e < 4; ++e) {
                            float v = vv[e];
                            if (v > thmin) {
                                stopv[tid*MCAND + minpos] = v;
                                stopi[tid*MCAND + minpos] = pbase + j*4 + e;
                                float mn = stopv[tid*MCAND]; int mp = 0;
#pragma unroll 8
                                for (int u = 1; u < MCAND; ++u) {
                                    float x = stopv[tid*MCAND + u];
                                    if (x < mn) { mn = x; mp = u; }
                                }
                                thmin = mn; minpos = mp;
                            }
                        }
                    }
                }
            }
        }
        __syncthreads();   // stage-reuse + Cs WAR safety
    }

    if (tid < 128) {
        size_t base = (size_t)(batch*NPTS + qb*128 + tid) * MCAND;
#pragma unroll
        for (int j = 0; j < MCAND; ++j) g_cand[base + j] = stopi[tid*MCAND + j];
    }
}

// ---------------- kernel 2: exact rescore, R1-bit-identical sequential fma ----
#define RS_CHUNK 128
__global__ __launch_bounds__(256) void rescore_kernel(float* __restrict__ out) {
    __shared__ int   sidx[MCAND];
    __shared__ float sfq[2][RS_CHUNK];
    __shared__ float sp[2][RS_CHUNK*33];
    const int qi    = blockIdx.x;          // 0..16383
    const int batch = qi >> 11;
    const int tid   = threadIdx.x, lane = tid & 31, warp = tid >> 5;

    if (tid < MCAND) sidx[tid] = g_cand[(size_t)qi*MCAND + tid];
    __syncthreads();

    const float* fq  = g_fqn + (size_t)qi * DIM;
    const float* fpb = g_fpn + (size_t)batch*NPTS*DIM;

    auto load_tile = [&](int buf, int ch, int tileid) {
        int row = (tileid & 7)*4 + (lane >> 3);
        int k4  = (tileid >> 3)*8 + (lane & 7);
        float4 v = *(const float4*)(fpb + (size_t)sidx[row]*DIM + ch*RS_CHUNK + k4*4);
        float* b = &sp[buf][0];
        b[(k4*4+0)*33 + row] = v.x;
        b[(k4*4+1)*33 + row] = v.y;
        b[(k4*4+2)*33 + row] = v.z;
        b[(k4*4+3)*33 + row] = v.w;
    };

    {
#pragma unroll
        for (int it = 0; it < 4; ++it) load_tile(0, 0, warp*4 + it);
        if (tid < 32) {
            float4 v = *(const float4*)(fq + tid*4);
            *(float4*)&sfq[0][tid*4] = v;
        }
    }
    __syncthreads();

    float acc = 0.f;
#pragma unroll
    for (int ch = 0; ch < DIM/RS_CHUNK; ++ch) {
        const int buf = ch & 1;
        if (warp == 0) {
            const float* b = &sp[buf][0];
            const float* f = &sfq[buf][0];
#pragma unroll
            for (int k = 0; k < RS_CHUNK; ++k)
                acc = fmaf(f[k], b[k*33 + lane], acc);   // strict k order
        } else if (ch + 1 < DIM/RS_CHUNK) {
            const int nb = buf ^ 1, wl = warp - 1;
#pragma unroll
            for (int it = 0; it < 5; ++it) {
                int tileid = wl*5 + it;
                if (tileid < 32) load_tile(nb, ch + 1, tileid);
            }
            if (warp == 7) {
                float4 v = *(const float4*)(fq + (ch+1)*RS_CHUNK + lane*4);
                *(float4*)&sfq[nb][lane*4] = v;
            }
        }
        __syncthreads();
    }

    if (warp == 0) {
        float v = acc; int idx = sidx[lane];
#pragma unroll
        for (int k = 2; k <= 32; k <<= 1) {
#pragma unroll
            for (int j = k >> 1; j > 0; j >>= 1) {
                float pv = __shfl_xor_sync(0xffffffffu, v, j);
                int   pi = __shfl_xor_sync(0xffffffffu, idx, j);
                bool up    = (lane & k) == 0;
                bool lower = (lane & j) == 0;
                bool pb    = (pv > v) || (pv == v && pi < idx);
                bool take  = (pb == (up == lower));
                if (take) { v = pv; idx = pi; }
            }
        }
        if (lane < KTOP) {
            g_topi[(size_t)qi*KTOP + lane] = idx;
            out[3*SEG + (size_t)qi*KTOP + lane] = (float)idx;
        }
    }
}

// ---------------- kernel 3: gather + pool + linear + rotate-back ------------
__device__ __forceinline__ void inv3(const float* __restrict__ R, float* o) {
    float a = R[0], b = R[1], c = R[2];
    float d = R[3], e = R[4], f = R[5];
    float g = R[6], h = R[7], i = R[8];
    float A =  (e*i - f*h);
    float Bc = -(d*i - f*g);
    float Cc =  (d*h - e*g);
    float det = a*A + b*Bc + c*Cc;
    float id = 1.f / det;
    o[0] = A*id;             o[1] = -(b*i - c*h)*id;  o[2] =  (b*f - c*e)*id;
    o[3] = Bc*id;            o[4] =  (a*i - c*g)*id;  o[5] = -(a*f - c*d)*id;
    o[6] = Cc*id;            o[7] = -(a*h - b*g)*id;  o[8] =  (a*e - b*d)*id;
}

__global__ void post_kernel(const float* __restrict__ q,
                            const float* __restrict__ ffq,
                            const float* __restrict__ ffp,
                            const float* __restrict__ R1,
                            const float* __restrict__ R2,
                            const int*   __restrict__ centroids,
                            const float* __restrict__ W,
                            const float* __restrict__ bias,
                            float* __restrict__ out) {
    const int pt    = blockIdx.x;
    const int batch = pt >> 11;
    const int tid   = threadIdx.x;       // 128 threads

    __shared__ int   sidx[KTOP];
    __shared__ float sred[3][4];

    if (tid < KTOP) sidx[tid] = g_topi[(size_t)pt*KTOP + tid];
    __syncthreads();

    const float* fpb = ffp + (size_t)batch*NPTS*DIM;
    float pv0 = 0.f, pv1 = 0.f, pv2 = 0.f;
#pragma unroll
    for (int r = 0; r < 4; ++r) {
        int d = tid + r*128;
        float fq = ffq[(size_t)pt*DIM + d];
        float s = 0.f, mx = -INFINITY;
#pragma unroll
        for (int k = 0; k < KTOP; ++k) {
            float v = fpb[(size_t)sidx[k]*DIM + d];
            s += v;
            mx = fmaxf(mx, v);
        }
        float avg = s * (1.f/KTOP);
        pv0 += W[0*1536 + d]*fq + W[0*1536 + 512 + d]*avg + W[0*1536 + 1024 + d]*mx;
        pv1 += W[1*1536 + d]*fq + W[1*1536 + 512 + d]*avg + W[1*1536 + 1024 + d]*mx;
        pv2 += W[2*1536 + d]*fq + W[2*1536 + 512 + d]*avg + W[2*1536 + 1024 + d]*mx;
    }
#pragma unroll
    for (int o = 16; o; o >>= 1) {
        pv0 += __shfl_xor_sync(0xffffffffu, pv0, o);
        pv1 += __shfl_xor_sync(0xffffffffu, pv1, o);
        pv2 += __shfl_xor_sync(0xffffffffu, pv2, o);
    }
    int lane = tid & 31, w = tid >> 5;
    if (lane == 0) { sred[0][w] = pv0; sred[1][w] = pv1; sred[2][w] = pv2; }
    __syncthreads();

    if (tid == 0) {
        float v0 = sred[0][0]+sred[0][1]+sred[0][2]+sred[0][3] + bias[0];
        float v1 = sred[1][0]+sred[1][1]+sred[1][2]+sred[1][3] + bias[1];
        float v2 = sred[2][0]+sred[2][1]+sred[2][2]+sred[2][3] + bias[2];
        float i1[9], i2[9];
        inv3(R1 + (size_t)pt*9, i1);
        inv3(R2 + (size_t)pt*9, i2);
        float t0 = i1[0]*v0 + i1[1]*v1 + i1[2]*v2;
        float t1 = i1[3]*v0 + i1[4]*v1 + i1[5]*v2;
        float t2 = i1[6]*v0 + i1[7]*v1 + i1[8]*v2;
        float r0 = i2[0]*t0 + i2[1]*t1 + i2[2]*t2;
        float r1 = i2[3]*t0 + i2[4]*t1 + i2[5]*t2;
        float r2 = i2[6]*t0 + i2[7]*t1 + i2[8]*t2;
        float m = (centroids[pt] >= NPTS) ? 1.f : 0.f;
        const float* qp = q + (size_t)pt*3;
        float o0 = qp[0] + r0*m;
        float o1 = qp[1] + r1*m;
        float o2 = qp[2] + r2*m;
        out[1*SEG + pt*3 + 0] = o0;
        out[1*SEG + pt*3 + 1] = o1;
        out[1*SEG + pt*3 + 2] = o2;
        out[2*SEG + pt*3 + 0] = o0;
        out[2*SEG + pt*3 + 1] = o1;
        out[2*SEG + pt*3 + 2] = o2;
    }
}

// ---------------- launch -----------------------------------------------------
extern "C" void kernel_launch(void* const* d_in, const int* in_sizes, int n_in,
                              void* d_out, int out_size) {
    const float* q    = (const float*)d_in[1];
    const float* ffp  = (const float*)d_in[2];
    const float* ffq  = (const float*)d_in[3];
    const float* R1   = (const float*)d_in[4];
    const float* R2   = (const float*)d_in[5];
    const int*   cent = (const int*)  d_in[6];
    const float* W    = (const float*)d_in[7];
    const float* bias = (const float*)d_in[8];
    float* out = (float*)d_out;

    cudaMemcpyAsync(out, q, (size_t)SEG*sizeof(float), cudaMemcpyDeviceToDevice);

    norm_kernel<<<BATCH*NPTS/8, 256>>>(ffq, 0);
    norm_kernel<<<BATCH*NPTS/8, 256>>>(ffp, 1);

    cudaFuncSetAttribute(gemm_topm,
                         cudaFuncAttributeMaxDynamicSharedMemorySize, SM_TOTAL);
    gemm_topm<<<dim3(NPTS/128, BATCH), 512, SM_TOTAL>>>();

    rescore_kernel<<<BATCH*NPTS, 256>>>(out);

    post_kernel<<<BATCH*NPTS, 128>>>(q, ffq, ffp, R1, R2, cent, W, bias, out);
}